// round 5
// baseline (speedup 1.0000x reference)
#include <cuda_runtime.h>
#include <cstdint>

#define F_IN   512
#define HF     256
#define OUTF   2
#define N_MAX  50000
#define E_MAX  800000
#define BN_EPS 1e-5f

// ---------------- scratch (device globals: no allocation allowed) ----------------
__device__ __align__(256) float g_bufA[(size_t)N_MAX * HF];   // GEMM outputs (h)
__device__ __align__(256) float g_bufB[(size_t)N_MAX * HF];   // aggregation outputs
__device__ __align__(256) float g_norm[E_MAX];                // per-edge norm
__device__ __align__(256) float g_dinv[N_MAX];                // deg -> dinv (in place)
__device__ __align__(256) float g_self[N_MAX];                // dinv^2 (self-loop norm)
__device__ __align__(256) float g_h3[(size_t)N_MAX * OUTF];
__device__ __align__(256) float g_scale1[HF], g_shift1[HF];
__device__ __align__(256) float g_scale2[HF], g_shift2[HF];

// ---------------- small prep kernels ----------------
__global__ void k_init_deg(float* deg, int n) {
    int i = blockIdx.x * blockDim.x + threadIdx.x;
    if (i < n) deg[i] = 1.0f;   // self-loop weight 1
}

__global__ void k_accum_deg(const int* __restrict__ col,
                            const float* __restrict__ w, float* deg, int e) {
    int i = blockIdx.x * blockDim.x + threadIdx.x;
    if (i < e) atomicAdd(&deg[col[i]], w[i]);
}

__global__ void k_finalize_deg(float* dinv, float* selfn, int n) {
    int i = blockIdx.x * blockDim.x + threadIdx.x;
    if (i < n) {
        float d = dinv[i];
        float r = rsqrtf(d);   // d >= 1 always (self-loop)
        dinv[i]  = r;
        selfn[i] = r * r;
    }
}

__global__ void k_edge_norm(const int* __restrict__ row,
                            const int* __restrict__ col,
                            const float* __restrict__ w,
                            const float* __restrict__ dinv,
                            float* __restrict__ norm, int e) {
    int i = blockIdx.x * blockDim.x + threadIdx.x;
    if (i < e) norm[i] = dinv[row[i]] * w[i] * dinv[col[i]];
}

__global__ void k_bn_prep(const float* __restrict__ g, const float* __restrict__ be,
                          const float* __restrict__ m, const float* __restrict__ v,
                          float* __restrict__ scale, float* __restrict__ shift) {
    int i = threadIdx.x;
    if (i < HF) {
        float s = g[i] * rsqrtf(v[i] + BN_EPS);
        scale[i] = s;
        shift[i] = be[i] - m[i] * s;
    }
}

// ---------------- SGEMM: C[M,N] = act(A)[M,K] @ B[K,N] ----------------
// act(a) = (scale ? relu(a*scale[k]+shift[k]) : a)   (BN+ReLU folded into A load)
#define BM 128
#define BN 128
#define BKK 16
#define TM 8
#define TN 8

__global__ __launch_bounds__(256) void sgemm_kernel(
    int M, int K, int N,
    const float* __restrict__ A,
    const float* __restrict__ B,
    float* __restrict__ C,
    const float* __restrict__ scale,
    const float* __restrict__ shift)
{
    __shared__ float As[BKK][BM + 4];   // transposed A tile (+pad: kill bank conflicts)
    __shared__ float Bs[BKK][BN];

    const int tid     = threadIdx.x;
    const int rowBase = blockIdx.y * BM;
    const int colBase = blockIdx.x * BN;

    const int aRow = tid >> 2;          // 0..63 (2 passes -> 128 rows)
    const int aCol = (tid & 3) * 4;     // 0,4,8,12
    const int bRow = tid >> 5;          // 0..7  (2 passes -> 16 k-rows)
    const int bCol = (tid & 31) * 4;    // 0..124

    const int tRow = (tid >> 4) * TM;
    const int tCol = (tid & 15) * TN;

    float acc[TM][TN];
#pragma unroll
    for (int i = 0; i < TM; i++)
#pragma unroll
        for (int j = 0; j < TN; j++) acc[i][j] = 0.0f;

    for (int k0 = 0; k0 < K; k0 += BKK) {
        // --- load A tile (apply BN+ReLU if requested) ---
#pragma unroll
        for (int p = 0; p < 2; p++) {
            int r = rowBase + aRow + p * 64;
            float4 v = make_float4(0.f, 0.f, 0.f, 0.f);
            if (r < M)
                v = *reinterpret_cast<const float4*>(A + (size_t)r * K + k0 + aCol);
            if (scale) {
                int kb = k0 + aCol;
                v.x = fmaxf(fmaf(v.x, scale[kb + 0], shift[kb + 0]), 0.f);
                v.y = fmaxf(fmaf(v.y, scale[kb + 1], shift[kb + 1]), 0.f);
                v.z = fmaxf(fmaf(v.z, scale[kb + 2], shift[kb + 2]), 0.f);
                v.w = fmaxf(fmaf(v.w, scale[kb + 3], shift[kb + 3]), 0.f);
            }
            As[aCol + 0][aRow + p * 64] = v.x;
            As[aCol + 1][aRow + p * 64] = v.y;
            As[aCol + 2][aRow + p * 64] = v.z;
            As[aCol + 3][aRow + p * 64] = v.w;
        }
        // --- load B tile ---
#pragma unroll
        for (int p = 0; p < 2; p++) {
            int kr = k0 + bRow + p * 8;
            float4 v = *reinterpret_cast<const float4*>(B + (size_t)kr * N + colBase + bCol);
            *reinterpret_cast<float4*>(&Bs[bRow + p * 8][bCol]) = v;
        }
        __syncthreads();

#pragma unroll
        for (int kk = 0; kk < BKK; kk++) {
            float ra[TM], rb[TN];
            float4 a0 = *reinterpret_cast<const float4*>(&As[kk][tRow]);
            float4 a1 = *reinterpret_cast<const float4*>(&As[kk][tRow + 4]);
            ra[0] = a0.x; ra[1] = a0.y; ra[2] = a0.z; ra[3] = a0.w;
            ra[4] = a1.x; ra[5] = a1.y; ra[6] = a1.z; ra[7] = a1.w;
            float4 b0 = *reinterpret_cast<const float4*>(&Bs[kk][tCol]);
            float4 b1 = *reinterpret_cast<const float4*>(&Bs[kk][tCol + 4]);
            rb[0] = b0.x; rb[1] = b0.y; rb[2] = b0.z; rb[3] = b0.w;
            rb[4] = b1.x; rb[5] = b1.y; rb[6] = b1.z; rb[7] = b1.w;
#pragma unroll
            for (int i = 0; i < TM; i++)
#pragma unroll
                for (int j = 0; j < TN; j++)
                    acc[i][j] = fmaf(ra[i], rb[j], acc[i][j]);
        }
        __syncthreads();
    }

#pragma unroll
    for (int i = 0; i < TM; i++) {
        int r = rowBase + tRow + i;
        if (r < M) {
            float4 o0 = make_float4(acc[i][0], acc[i][1], acc[i][2], acc[i][3]);
            float4 o1 = make_float4(acc[i][4], acc[i][5], acc[i][6], acc[i][7]);
            *reinterpret_cast<float4*>(C + (size_t)r * N + colBase + tCol)     = o0;
            *reinterpret_cast<float4*>(C + (size_t)r * N + colBase + tCol + 4) = o1;
        }
    }
}

// ---------------- aggregation: init with bias + self-loop term ----------------
__global__ void k_agg_init(const float* __restrict__ h, const float* __restrict__ bias,
                           float* __restrict__ out, int n)
{
    int idx = blockIdx.x * blockDim.x + threadIdx.x;   // n * 64 float4s
    if (idx >= n * (HF / 4)) return;
    int i = idx >> 6;
    int f = idx & 63;
    float s = g_self[i];
    float4 hv = reinterpret_cast<const float4*>(h)[idx];
    float4 bv = reinterpret_cast<const float4*>(bias)[f];
    float4 o  = make_float4(fmaf(s, hv.x, bv.x), fmaf(s, hv.y, bv.y),
                            fmaf(s, hv.z, bv.z), fmaf(s, hv.w, bv.w));
    reinterpret_cast<float4*>(out)[idx] = o;
}

// ---------------- edge scatter: out[col] += norm * h[row]  (F = 256) ----------------
__device__ __forceinline__ void red_add_v4(float* p, float4 v) {
    asm volatile("red.global.add.v4.f32 [%0], {%1, %2, %3, %4};"
                 :: "l"(p), "f"(v.x), "f"(v.y), "f"(v.z), "f"(v.w)
                 : "memory");
}

__global__ void k_scatter(const float* __restrict__ h, float* __restrict__ out,
                          const int* __restrict__ row,
                          const int* __restrict__ col,
                          const float* __restrict__ norm, int e)
{
    int warp = (blockIdx.x * blockDim.x + threadIdx.x) >> 5;
    int lane = threadIdx.x & 31;
    if (warp >= e) return;
    int r = row[warp];
    int c = col[warp];
    float nm = norm[warp];
    const float4* hp = reinterpret_cast<const float4*>(h + (size_t)r * HF);
    float* op = out + (size_t)c * HF;
#pragma unroll
    for (int p = 0; p < 2; p++) {
        int f4 = lane + p * 32;
        float4 v = hp[f4];
        red_add_v4(op + f4 * 4, make_float4(v.x * nm, v.y * nm, v.z * nm, v.w * nm));
    }
}

// ---------------- layer 3: skinny GEMM (256 -> 2) with fused BN2+ReLU ----------------
__global__ void k_gemm3(const float* __restrict__ A, const float* __restrict__ W3,
                        float* __restrict__ h3, int M)
{
    __shared__ float w0[HF], w1[HF];
    for (int i = threadIdx.x; i < HF; i += blockDim.x) {
        w0[i] = W3[i * 2 + 0];
        w1[i] = W3[i * 2 + 1];
    }
    __syncthreads();
    int gw   = (blockIdx.x * blockDim.x + threadIdx.x) >> 5;
    int lane = threadIdx.x & 31;
    if (gw >= M) return;
    const float* a = A + (size_t)gw * HF;
    float acc0 = 0.f, acc1 = 0.f;
#pragma unroll
    for (int j = 0; j < HF / 32; j++) {
        int k = j * 32 + lane;
        float av = fmaxf(fmaf(a[k], g_scale2[k], g_shift2[k]), 0.f);
        acc0 = fmaf(av, w0[k], acc0);
        acc1 = fmaf(av, w1[k], acc1);
    }
#pragma unroll
    for (int off = 16; off; off >>= 1) {
        acc0 += __shfl_xor_sync(0xffffffffu, acc0, off);
        acc1 += __shfl_xor_sync(0xffffffffu, acc1, off);
    }
    if (lane == 0) {
        h3[gw * 2 + 0] = acc0;
        h3[gw * 2 + 1] = acc1;
    }
}

__global__ void k_out_init3(const float* __restrict__ h3, const float* __restrict__ b3,
                            float* __restrict__ out, int n)
{
    int i = blockIdx.x * blockDim.x + threadIdx.x;
    if (i >= n) return;
    float s = g_self[i];
    out[i * 2 + 0] = fmaf(s, h3[i * 2 + 0], b3[0]);
    out[i * 2 + 1] = fmaf(s, h3[i * 2 + 1], b3[1]);
}

__global__ void k_scatter3(const float* __restrict__ h3, float* __restrict__ out,
                           const int* __restrict__ row,
                           const int* __restrict__ col,
                           const float* __restrict__ norm, int e)
{
    int i = blockIdx.x * blockDim.x + threadIdx.x;
    if (i >= e) return;
    int r = row[i];
    int c = col[i];
    float nm = norm[i];
    atomicAdd(&out[c * 2 + 0], nm * h3[r * 2 + 0]);
    atomicAdd(&out[c * 2 + 1], nm * h3[r * 2 + 1]);
}

// ---------------- driver ----------------
extern "C" void kernel_launch(void* const* d_in, const int* in_sizes, int n_in,
                              void* d_out, int out_size)
{
    const float* x   = (const float*)d_in[0];
    const int*   ei  = (const int*)d_in[1];     // int32! (JAX x64 disabled)
    const float* ew  = (const float*)d_in[2];
    const float* W1  = (const float*)d_in[3];
    const float* b1  = (const float*)d_in[4];
    const float* g1  = (const float*)d_in[5];
    const float* be1 = (const float*)d_in[6];
    const float* m1  = (const float*)d_in[7];
    const float* v1  = (const float*)d_in[8];
    const float* W2  = (const float*)d_in[9];
    const float* b2  = (const float*)d_in[10];
    const float* g2  = (const float*)d_in[11];
    const float* be2 = (const float*)d_in[12];
    const float* m2  = (const float*)d_in[13];
    const float* v2  = (const float*)d_in[14];
    const float* W3  = (const float*)d_in[15];
    const float* b3  = (const float*)d_in[16];
    float* out = (float*)d_out;

    const int n = in_sizes[0] / F_IN;
    const int e = in_sizes[2];

    float *bufA, *bufB, *norm, *dinv, *selfn, *h3, *sc1, *sh1, *sc2, *sh2;
    cudaGetSymbolAddress((void**)&bufA,  g_bufA);
    cudaGetSymbolAddress((void**)&bufB,  g_bufB);
    cudaGetSymbolAddress((void**)&norm,  g_norm);
    cudaGetSymbolAddress((void**)&dinv,  g_dinv);
    cudaGetSymbolAddress((void**)&selfn, g_self);
    cudaGetSymbolAddress((void**)&h3,    g_h3);
    cudaGetSymbolAddress((void**)&sc1,   g_scale1);
    cudaGetSymbolAddress((void**)&sh1,   g_shift1);
    cudaGetSymbolAddress((void**)&sc2,   g_scale2);
    cudaGetSymbolAddress((void**)&sh2,   g_shift2);

    const int* row = ei;
    const int* col = ei + e;

    const int T = 256;
    // --- prep: degrees + norms + BN fold (shared by all 3 conv layers) ---
    k_init_deg    <<<(n + T - 1) / T, T>>>(dinv, n);
    k_accum_deg   <<<(e + T - 1) / T, T>>>(col, ew, dinv, e);
    k_finalize_deg<<<(n + T - 1) / T, T>>>(dinv, selfn, n);
    k_edge_norm   <<<(e + T - 1) / T, T>>>(row, col, ew, dinv, norm, e);
    k_bn_prep     <<<1, HF>>>(g1, be1, m1, v1, sc1, sh1);
    k_bn_prep     <<<1, HF>>>(g2, be2, m2, v2, sc2, sh2);

    dim3 gemmGrid(HF / BN, (n + BM - 1) / BM);

    // --- layer 1: h = x @ W1; agg = b1 + self*h + scatter ---
    sgemm_kernel<<<gemmGrid, 256>>>(n, F_IN, HF, x, W1, bufA, nullptr, nullptr);
    k_agg_init<<<(n * (HF / 4) + T - 1) / T, T>>>(bufA, b1, bufB, n);
    k_scatter <<<((size_t)e * 32 + T - 1) / T, T>>>(bufA, bufB, row, col, norm, e);

    // --- layer 2: h = relu(bn1(agg)) @ W2; agg = b2 + self*h + scatter ---
    sgemm_kernel<<<gemmGrid, 256>>>(n, HF, HF, bufB, W2, bufA, sc1, sh1);
    k_agg_init<<<(n * (HF / 4) + T - 1) / T, T>>>(bufA, b2, bufB, n);
    k_scatter <<<((size_t)e * 32 + T - 1) / T, T>>>(bufA, bufB, row, col, norm, e);

    // --- layer 3: h3 = relu(bn2(agg)) @ W3; out = b3 + self*h3 + scatter ---
    k_gemm3    <<<((size_t)n * 32 + T - 1) / T, T>>>(bufB, W3, h3, n);
    k_out_init3<<<(n + T - 1) / T, T>>>(h3, b3, out, n);
    k_scatter3 <<<(e + T - 1) / T, T>>>(h3, out, row, col, norm, e);
}

// round 6
// speedup vs baseline: 1.0768x; 1.0768x over previous
#include <cuda_runtime.h>
#include <cstdint>

#define F_IN   512
#define HF     256
#define OUTF   2
#define N_MAX  50000
#define E_MAX  800000
#define BN_EPS 1e-5f

// ---------------- scratch (device globals: no allocation allowed) ----------------
__device__ __align__(256) float g_bufA[(size_t)N_MAX * HF];   // GEMM outputs (h)
__device__ __align__(256) float g_bufB[(size_t)N_MAX * HF];   // aggregation outputs
__device__ __align__(256) float g_norm[E_MAX];                // per-edge norm
__device__ __align__(256) float g_dinv[N_MAX];                // deg -> dinv (in place)
__device__ __align__(256) float g_self[N_MAX];                // dinv^2 (self-loop norm)
__device__ __align__(256) float g_h3[(size_t)N_MAX * OUTF];
__device__ __align__(256) float g_scale1[HF], g_shift1[HF];
__device__ __align__(256) float g_scale2[HF], g_shift2[HF];

// ---------------- small prep kernels ----------------
__global__ void k_init_deg(float* deg, int n) {
    int i = blockIdx.x * blockDim.x + threadIdx.x;
    if (i < n) deg[i] = 1.0f;   // self-loop weight 1
}

__global__ void k_accum_deg(const int* __restrict__ col,
                            const float* __restrict__ w, float* deg, int e) {
    int i = blockIdx.x * blockDim.x + threadIdx.x;
    if (i < e) atomicAdd(&deg[col[i]], w[i]);
}

__global__ void k_finalize_deg(float* dinv, float* selfn, int n) {
    int i = blockIdx.x * blockDim.x + threadIdx.x;
    if (i < n) {
        float d = dinv[i];
        float r = rsqrtf(d);   // d >= 1 always (self-loop)
        dinv[i]  = r;
        selfn[i] = r * r;
    }
}

__global__ void k_edge_norm(const int* __restrict__ row,
                            const int* __restrict__ col,
                            const float* __restrict__ w,
                            const float* __restrict__ dinv,
                            float* __restrict__ norm, int e) {
    int i = blockIdx.x * blockDim.x + threadIdx.x;
    if (i < e) norm[i] = dinv[row[i]] * w[i] * dinv[col[i]];
}

__global__ void k_bn_prep(const float* __restrict__ g, const float* __restrict__ be,
                          const float* __restrict__ m, const float* __restrict__ v,
                          float* __restrict__ scale, float* __restrict__ shift) {
    int i = threadIdx.x;
    if (i < HF) {
        float s = g[i] * rsqrtf(v[i] + BN_EPS);
        scale[i] = s;
        shift[i] = be[i] - m[i] * s;
    }
}

// ---------------- 3xTF32 tensor-core GEMM: C = act(A)[M,K] @ B[K,N] ----------------
// act = relu(a*scale[k]+shift[k]) when scale != null (BN+ReLU folded into A load).
// CTA tile 128x128, 8 warps of 64x32, BK=16, double-buffered smem.
// Precision: a = aHi + aLo (tf32 split); acc += aHi*bHi + aHi*bLo + aLo*bHi  (~2^-22 rel err)

__device__ __forceinline__ void split_tf32(float v, uint32_t& hi, uint32_t& lo) {
    uint32_t h;
    asm("cvt.rna.tf32.f32 %0, %1;" : "=r"(h) : "f"(v));
    float lf = v - __uint_as_float(h);
    asm("cvt.rna.tf32.f32 %0, %1;" : "=r"(lo) : "f"(lf));
    hi = h;
}

__device__ __forceinline__ void mma1688(float* c, const uint32_t* a, const uint32_t* b) {
    asm volatile(
        "mma.sync.aligned.m16n8k8.row.col.f32.tf32.tf32.f32 "
        "{%0,%1,%2,%3}, {%4,%5,%6,%7}, {%8,%9}, {%0,%1,%2,%3};"
        : "+f"(c[0]), "+f"(c[1]), "+f"(c[2]), "+f"(c[3])
        : "r"(a[0]), "r"(a[1]), "r"(a[2]), "r"(a[3]), "r"(b[0]), "r"(b[1]));
}

#define GBM 128
#define GBN 128
#define GBK 16
#define APAD 20    // row stride of As in floats (80B: float4-aligned, conflict-light)
#define BPAD 132   // row stride of Bs in floats (528B: float4-aligned)

__global__ __launch_bounds__(256) void tf32_gemm(
    int M, int K, int N,
    const float* __restrict__ A,
    const float* __restrict__ B,
    float* __restrict__ C,
    const float* __restrict__ scale,
    const float* __restrict__ shift)
{
    __shared__ float As[2][GBM][APAD];   // [row][k]
    __shared__ float Bs[2][GBK][BPAD];   // [k][n]

    const int tid  = threadIdx.x;
    const int lane = tid & 31;
    const int warp = tid >> 5;
    const int wRow = (warp & 1) * 64;    // warp tile: 64 rows x 32 cols
    const int wCol = (warp >> 1) * 32;
    const int ctaRow = blockIdx.y * GBM;
    const int ctaCol = blockIdx.x * GBN;
    const int grp = lane >> 2;           // 0..7
    const int tig = lane & 3;            // 0..3

    // global->smem staging indices
    const int aRow = tid >> 2;           // 0..63 (x2 passes)
    const int aCol = (tid & 3) * 4;      // 0,4,8,12
    const int bK   = tid >> 5;           // 0..7  (x2 passes)
    const int bN   = (tid & 31) * 4;     // 0..124

    float acc[4][4][4];
#pragma unroll
    for (int t = 0; t < 4; t++)
#pragma unroll
        for (int u = 0; u < 4; u++)
#pragma unroll
            for (int i = 0; i < 4; i++) acc[t][u][i] = 0.0f;

    float4 pa[2], pb[2];

    auto loadTile = [&](int k0) {
#pragma unroll
        for (int p = 0; p < 2; p++) {
            int r = ctaRow + aRow + p * 64;
            float4 v = make_float4(0.f, 0.f, 0.f, 0.f);
            if (r < M)
                v = *reinterpret_cast<const float4*>(A + (size_t)r * K + k0 + aCol);
            if (scale) {
                int kb = k0 + aCol;
                v.x = fmaxf(fmaf(v.x, scale[kb + 0], shift[kb + 0]), 0.f);
                v.y = fmaxf(fmaf(v.y, scale[kb + 1], shift[kb + 1]), 0.f);
                v.z = fmaxf(fmaf(v.z, scale[kb + 2], shift[kb + 2]), 0.f);
                v.w = fmaxf(fmaf(v.w, scale[kb + 3], shift[kb + 3]), 0.f);
            }
            pa[p] = v;
            pb[p] = *reinterpret_cast<const float4*>(
                B + (size_t)(k0 + bK + p * 8) * N + ctaCol + bN);
        }
    };

    auto storeTile = [&](int buf) {
#pragma unroll
        for (int p = 0; p < 2; p++) {
            *reinterpret_cast<float4*>(&As[buf][aRow + p * 64][aCol]) = pa[p];
            *reinterpret_cast<float4*>(&Bs[buf][bK + p * 8][bN])      = pb[p];
        }
    };

    auto computeTile = [&](int buf) {
#pragma unroll
        for (int ks8 = 0; ks8 < 2; ks8++) {
            const int ks = ks8 * 8;
            uint32_t aHi[4][4], aLo[4][4];
#pragma unroll
            for (int t = 0; t < 4; t++) {
                int r = wRow + 16 * t + grp;
                float v0 = As[buf][r    ][ks + tig];
                float v1 = As[buf][r + 8][ks + tig];
                float v2 = As[buf][r    ][ks + tig + 4];
                float v3 = As[buf][r + 8][ks + tig + 4];
                split_tf32(v0, aHi[t][0], aLo[t][0]);
                split_tf32(v1, aHi[t][1], aLo[t][1]);
                split_tf32(v2, aHi[t][2], aLo[t][2]);
                split_tf32(v3, aHi[t][3], aLo[t][3]);
            }
            uint32_t bHi[4][2], bLo[4][2];
#pragma unroll
            for (int u = 0; u < 4; u++) {
                int c = wCol + 8 * u + grp;
                float w0 = Bs[buf][ks + tig    ][c];
                float w1 = Bs[buf][ks + tig + 4][c];
                split_tf32(w0, bHi[u][0], bLo[u][0]);
                split_tf32(w1, bHi[u][1], bLo[u][1]);
            }
#pragma unroll
            for (int t = 0; t < 4; t++)
#pragma unroll
                for (int u = 0; u < 4; u++) {
                    mma1688(acc[t][u], aLo[t], bHi[u]);
                    mma1688(acc[t][u], aHi[t], bLo[u]);
                    mma1688(acc[t][u], aHi[t], bHi[u]);
                }
        }
    };

    const int nT = K / GBK;
    loadTile(0);
    storeTile(0);
    __syncthreads();
    for (int it = 0; it < nT; it++) {
        if (it + 1 < nT) loadTile((it + 1) * GBK);
        computeTile(it & 1);
        if (it + 1 < nT) storeTile((it + 1) & 1);
        __syncthreads();
    }

    // epilogue
#pragma unroll
    for (int t = 0; t < 4; t++) {
        int r0 = ctaRow + wRow + 16 * t + grp;
#pragma unroll
        for (int u = 0; u < 4; u++) {
            int c0 = ctaCol + wCol + 8 * u + tig * 2;
            if (r0 < M)
                *reinterpret_cast<float2*>(C + (size_t)r0 * N + c0) =
                    make_float2(acc[t][u][0], acc[t][u][1]);
            if (r0 + 8 < M)
                *reinterpret_cast<float2*>(C + (size_t)(r0 + 8) * N + c0) =
                    make_float2(acc[t][u][2], acc[t][u][3]);
        }
    }
}

// ---------------- aggregation: init with bias + self-loop term ----------------
__global__ void k_agg_init(const float* __restrict__ h, const float* __restrict__ bias,
                           float* __restrict__ out, int n)
{
    int idx = blockIdx.x * blockDim.x + threadIdx.x;   // n * 64 float4s
    if (idx >= n * (HF / 4)) return;
    int i = idx >> 6;
    int f = idx & 63;
    float s = g_self[i];
    float4 hv = reinterpret_cast<const float4*>(h)[idx];
    float4 bv = reinterpret_cast<const float4*>(bias)[f];
    float4 o  = make_float4(fmaf(s, hv.x, bv.x), fmaf(s, hv.y, bv.y),
                            fmaf(s, hv.z, bv.z), fmaf(s, hv.w, bv.w));
    reinterpret_cast<float4*>(out)[idx] = o;
}

// ---------------- edge scatter: out[col] += norm * h[row]  (F = 256) ----------------
__device__ __forceinline__ void red_add_v4(float* p, float4 v) {
    asm volatile("red.global.add.v4.f32 [%0], {%1, %2, %3, %4};"
                 :: "l"(p), "f"(v.x), "f"(v.y), "f"(v.z), "f"(v.w)
                 : "memory");
}

__global__ void k_scatter(const float* __restrict__ h, float* __restrict__ out,
                          const int* __restrict__ row,
                          const int* __restrict__ col,
                          const float* __restrict__ norm, int e)
{
    int warp = (blockIdx.x * blockDim.x + threadIdx.x) >> 5;
    int lane = threadIdx.x & 31;
    if (warp >= e) return;
    int r = row[warp];
    int c = col[warp];
    float nm = norm[warp];
    const float4* hp = reinterpret_cast<const float4*>(h + (size_t)r * HF);
    float* op = out + (size_t)c * HF;
#pragma unroll
    for (int p = 0; p < 2; p++) {
        int f4 = lane + p * 32;
        float4 v = hp[f4];
        red_add_v4(op + f4 * 4, make_float4(v.x * nm, v.y * nm, v.z * nm, v.w * nm));
    }
}

// ---------------- layer 3: skinny GEMM (256 -> 2) with fused BN2+ReLU ----------------
__global__ void k_gemm3(const float* __restrict__ A, const float* __restrict__ W3,
                        float* __restrict__ h3, int M)
{
    __shared__ float w0[HF], w1[HF];
    for (int i = threadIdx.x; i < HF; i += blockDim.x) {
        w0[i] = W3[i * 2 + 0];
        w1[i] = W3[i * 2 + 1];
    }
    __syncthreads();
    int gw   = (blockIdx.x * blockDim.x + threadIdx.x) >> 5;
    int lane = threadIdx.x & 31;
    if (gw >= M) return;
    const float* a = A + (size_t)gw * HF;
    float acc0 = 0.f, acc1 = 0.f;
#pragma unroll
    for (int j = 0; j < HF / 32; j++) {
        int k = j * 32 + lane;
        float av = fmaxf(fmaf(a[k], g_scale2[k], g_shift2[k]), 0.f);
        acc0 = fmaf(av, w0[k], acc0);
        acc1 = fmaf(av, w1[k], acc1);
    }
#pragma unroll
    for (int off = 16; off; off >>= 1) {
        acc0 += __shfl_xor_sync(0xffffffffu, acc0, off);
        acc1 += __shfl_xor_sync(0xffffffffu, acc1, off);
    }
    if (lane == 0) {
        h3[gw * 2 + 0] = acc0;
        h3[gw * 2 + 1] = acc1;
    }
}

__global__ void k_out_init3(const float* __restrict__ h3, const float* __restrict__ b3,
                            float* __restrict__ out, int n)
{
    int i = blockIdx.x * blockDim.x + threadIdx.x;
    if (i >= n) return;
    float s = g_self[i];
    out[i * 2 + 0] = fmaf(s, h3[i * 2 + 0], b3[0]);
    out[i * 2 + 1] = fmaf(s, h3[i * 2 + 1], b3[1]);
}

__global__ void k_scatter3(const float* __restrict__ h3, float* __restrict__ out,
                           const int* __restrict__ row,
                           const int* __restrict__ col,
                           const float* __restrict__ norm, int e)
{
    int i = blockIdx.x * blockDim.x + threadIdx.x;
    if (i >= e) return;
    int r = row[i];
    int c = col[i];
    float nm = norm[i];
    atomicAdd(&out[c * 2 + 0], nm * h3[r * 2 + 0]);
    atomicAdd(&out[c * 2 + 1], nm * h3[r * 2 + 1]);
}

// ---------------- driver ----------------
extern "C" void kernel_launch(void* const* d_in, const int* in_sizes, int n_in,
                              void* d_out, int out_size)
{
    const float* x   = (const float*)d_in[0];
    const int*   ei  = (const int*)d_in[1];     // int32 (JAX x64 disabled)
    const float* ew  = (const float*)d_in[2];
    const float* W1  = (const float*)d_in[3];
    const float* b1  = (const float*)d_in[4];
    const float* g1  = (const float*)d_in[5];
    const float* be1 = (const float*)d_in[6];
    const float* m1  = (const float*)d_in[7];
    const float* v1  = (const float*)d_in[8];
    const float* W2  = (const float*)d_in[9];
    const float* b2  = (const float*)d_in[10];
    const float* g2  = (const float*)d_in[11];
    const float* be2 = (const float*)d_in[12];
    const float* m2  = (const float*)d_in[13];
    const float* v2  = (const float*)d_in[14];
    const float* W3  = (const float*)d_in[15];
    const float* b3  = (const float*)d_in[16];
    float* out = (float*)d_out;

    const int n = in_sizes[0] / F_IN;
    const int e = in_sizes[2];

    float *bufA, *bufB, *norm, *dinv, *selfn, *h3, *sc1, *sh1, *sc2, *sh2;
    cudaGetSymbolAddress((void**)&bufA,  g_bufA);
    cudaGetSymbolAddress((void**)&bufB,  g_bufB);
    cudaGetSymbolAddress((void**)&norm,  g_norm);
    cudaGetSymbolAddress((void**)&dinv,  g_dinv);
    cudaGetSymbolAddress((void**)&selfn, g_self);
    cudaGetSymbolAddress((void**)&h3,    g_h3);
    cudaGetSymbolAddress((void**)&sc1,   g_scale1);
    cudaGetSymbolAddress((void**)&sh1,   g_shift1);
    cudaGetSymbolAddress((void**)&sc2,   g_scale2);
    cudaGetSymbolAddress((void**)&sh2,   g_shift2);

    const int* row = ei;
    const int* col = ei + e;

    const int T = 256;
    // --- prep: degrees + norms + BN fold (shared by all 3 conv layers) ---
    k_init_deg    <<<(n + T - 1) / T, T>>>(dinv, n);
    k_accum_deg   <<<(e + T - 1) / T, T>>>(col, ew, dinv, e);
    k_finalize_deg<<<(n + T - 1) / T, T>>>(dinv, selfn, n);
    k_edge_norm   <<<(e + T - 1) / T, T>>>(row, col, ew, dinv, norm, e);
    k_bn_prep     <<<1, HF>>>(g1, be1, m1, v1, sc1, sh1);
    k_bn_prep     <<<1, HF>>>(g2, be2, m2, v2, sc2, sh2);

    dim3 gemmGrid(HF / GBN, (n + GBM - 1) / GBM);

    // --- layer 1: h = x @ W1; agg = b1 + self*h + scatter ---
    tf32_gemm<<<gemmGrid, 256>>>(n, F_IN, HF, x, W1, bufA, nullptr, nullptr);
    k_agg_init<<<(n * (HF / 4) + T - 1) / T, T>>>(bufA, b1, bufB, n);
    k_scatter <<<((size_t)e * 32 + T - 1) / T, T>>>(bufA, bufB, row, col, norm, e);

    // --- layer 2: h = relu(bn1(agg)) @ W2; agg = b2 + self*h + scatter ---
    tf32_gemm<<<gemmGrid, 256>>>(n, HF, HF, bufB, W2, bufA, sc1, sh1);
    k_agg_init<<<(n * (HF / 4) + T - 1) / T, T>>>(bufA, b2, bufB, n);
    k_scatter <<<((size_t)e * 32 + T - 1) / T, T>>>(bufA, bufB, row, col, norm, e);

    // --- layer 3: h3 = relu(bn2(agg)) @ W3; out = b3 + self*h3 + scatter ---
    k_gemm3    <<<((size_t)n * 32 + T - 1) / T, T>>>(bufB, W3, h3, n);
    k_out_init3<<<(n + T - 1) / T, T>>>(h3, b3, out, n);
    k_scatter3 <<<(e + T - 1) / T, T>>>(h3, out, row, col, norm, e);
}

// round 7
// speedup vs baseline: 1.3123x; 1.2187x over previous
#include <cuda_runtime.h>
#include <cstdint>

#define F_IN   512
#define HF     256
#define OUTF   2
#define N_MAX  50000
#define E_MAX  800000
#define BN_EPS 1e-5f

// ---------------- scratch (device globals: no allocation allowed) ----------------
__device__ __align__(256) float g_bufA[(size_t)N_MAX * HF];   // GEMM outputs (h)
__device__ __align__(256) float g_bufB[(size_t)N_MAX * HF];   // aggregation outputs
__device__ __align__(256) float g_dinv[N_MAX];                // weighted deg -> dinv (in place)
__device__ __align__(256) float g_self[N_MAX];                // dinv^2 (self-loop norm)
__device__ __align__(256) float g_h3[(size_t)N_MAX * OUTF];
__device__ __align__(256) float g_scale1[HF], g_shift1[HF];
__device__ __align__(256) float g_scale2[HF], g_shift2[HF];
// CSR-by-destination
__device__ __align__(256) int   g_degi[N_MAX];     // int in-degree (no self-loop)
__device__ __align__(256) int   g_rowptr[N_MAX + 1];
__device__ __align__(256) int   g_cursor[N_MAX];
__device__ __align__(256) int   g_crow[E_MAX];     // source node per CSR slot
__device__ __align__(256) float g_cnorm[E_MAX];    // edge norm per CSR slot

// ---------------- prep kernels ----------------
__global__ void k_init(float* degw, int* degi, int* cursor, int n) {
    int i = blockIdx.x * blockDim.x + threadIdx.x;
    if (i < n) { degw[i] = 1.0f; degi[i] = 0; cursor[i] = 0; }
}

__global__ void k_count(const int* __restrict__ col, const float* __restrict__ w,
                        float* degw, int* degi, int e) {
    int i = blockIdx.x * blockDim.x + threadIdx.x;
    if (i < e) {
        int c = col[i];
        atomicAdd(&degw[c], w[i]);
        atomicAdd(&degi[c], 1);
    }
}

__global__ void k_finalize_deg(float* dinv, float* selfn, int n) {
    int i = blockIdx.x * blockDim.x + threadIdx.x;
    if (i < n) {
        float d = dinv[i];
        float r = rsqrtf(d);   // d >= 1 (self-loop weight 1)
        dinv[i]  = r;
        selfn[i] = r * r;
    }
}

// single-block exclusive scan over degi -> rowptr (n up to 50k)
__global__ void k_scan(const int* __restrict__ degi, int* __restrict__ rowptr, int n) {
    __shared__ int warpsums[32];
    __shared__ int carry;
    if (threadIdx.x == 0) carry = 0;
    __syncthreads();
    const int lane = threadIdx.x & 31, w = threadIdx.x >> 5;
    for (int base = 0; base < n; base += 1024) {
        int i = base + (int)threadIdx.x;
        int v = (i < n) ? degi[i] : 0;
        int s = v;
#pragma unroll
        for (int o = 1; o < 32; o <<= 1) {
            int t = __shfl_up_sync(0xffffffffu, s, o);
            if (lane >= o) s += t;
        }
        if (lane == 31) warpsums[w] = s;
        __syncthreads();
        if (w == 0) {
            int ws = warpsums[lane];
#pragma unroll
            for (int o = 1; o < 32; o <<= 1) {
                int t = __shfl_up_sync(0xffffffffu, ws, o);
                if (lane >= o) ws += t;
            }
            warpsums[lane] = ws;
        }
        __syncthreads();
        int incl = s + (w > 0 ? warpsums[w - 1] : 0) + carry;
        if (i < n) rowptr[i + 1] = incl;
        __syncthreads();
        if (threadIdx.x == 1023) carry = incl;
        __syncthreads();
    }
    if (threadIdx.x == 0) rowptr[0] = 0;
}

__global__ void k_permute(const int* __restrict__ row, const int* __restrict__ col,
                          const float* __restrict__ w, const float* __restrict__ dinv,
                          const int* __restrict__ rowptr, int* cursor,
                          int* __restrict__ crow, float* __restrict__ cnorm, int e) {
    int i = blockIdx.x * blockDim.x + threadIdx.x;
    if (i < e) {
        int c = col[i];
        int r = row[i];
        int p = rowptr[c] + atomicAdd(&cursor[c], 1);
        crow[p]  = r;
        cnorm[p] = dinv[r] * w[i] * dinv[c];
    }
}

__global__ void k_bn_prep(const float* __restrict__ g, const float* __restrict__ be,
                          const float* __restrict__ m, const float* __restrict__ v,
                          float* __restrict__ scale, float* __restrict__ shift) {
    int i = threadIdx.x;
    if (i < HF) {
        float s = g[i] * rsqrtf(v[i] + BN_EPS);
        scale[i] = s;
        shift[i] = be[i] - m[i] * s;
    }
}

// ---------------- 3xTF32 tensor-core GEMM: C = act(A)[M,K] @ B[K,N] ----------------
__device__ __forceinline__ void split_tf32(float v, uint32_t& hi, uint32_t& lo) {
    uint32_t h;
    asm("cvt.rna.tf32.f32 %0, %1;" : "=r"(h) : "f"(v));
    float lf = v - __uint_as_float(h);
    asm("cvt.rna.tf32.f32 %0, %1;" : "=r"(lo) : "f"(lf));
    hi = h;
}

__device__ __forceinline__ void mma1688(float* c, const uint32_t* a, const uint32_t* b) {
    asm volatile(
        "mma.sync.aligned.m16n8k8.row.col.f32.tf32.tf32.f32 "
        "{%0,%1,%2,%3}, {%4,%5,%6,%7}, {%8,%9}, {%0,%1,%2,%3};"
        : "+f"(c[0]), "+f"(c[1]), "+f"(c[2]), "+f"(c[3])
        : "r"(a[0]), "r"(a[1]), "r"(a[2]), "r"(a[3]), "r"(b[0]), "r"(b[1]));
}

#define GBM 128
#define GBN 128
#define GBK 16
#define APAD 20
#define BPAD 132

__global__ __launch_bounds__(256) void tf32_gemm(
    int M, int K, int N,
    const float* __restrict__ A,
    const float* __restrict__ B,
    float* __restrict__ C,
    const float* __restrict__ scale,
    const float* __restrict__ shift)
{
    __shared__ float As[2][GBM][APAD];
    __shared__ float Bs[2][GBK][BPAD];

    const int tid  = threadIdx.x;
    const int lane = tid & 31;
    const int warp = tid >> 5;
    const int wRow = (warp & 1) * 64;
    const int wCol = (warp >> 1) * 32;
    const int ctaRow = blockIdx.y * GBM;
    const int ctaCol = blockIdx.x * GBN;
    const int grp = lane >> 2;
    const int tig = lane & 3;

    const int aRow = tid >> 2;
    const int aCol = (tid & 3) * 4;
    const int bK   = tid >> 5;
    const int bN   = (tid & 31) * 4;

    float acc[4][4][4];
#pragma unroll
    for (int t = 0; t < 4; t++)
#pragma unroll
        for (int u = 0; u < 4; u++)
#pragma unroll
            for (int i = 0; i < 4; i++) acc[t][u][i] = 0.0f;

    float4 pa[2], pb[2];

    auto loadTile = [&](int k0) {
#pragma unroll
        for (int p = 0; p < 2; p++) {
            int r = ctaRow + aRow + p * 64;
            float4 v = make_float4(0.f, 0.f, 0.f, 0.f);
            if (r < M)
                v = *reinterpret_cast<const float4*>(A + (size_t)r * K + k0 + aCol);
            if (scale) {
                int kb = k0 + aCol;
                v.x = fmaxf(fmaf(v.x, scale[kb + 0], shift[kb + 0]), 0.f);
                v.y = fmaxf(fmaf(v.y, scale[kb + 1], shift[kb + 1]), 0.f);
                v.z = fmaxf(fmaf(v.z, scale[kb + 2], shift[kb + 2]), 0.f);
                v.w = fmaxf(fmaf(v.w, scale[kb + 3], shift[kb + 3]), 0.f);
            }
            pa[p] = v;
            pb[p] = *reinterpret_cast<const float4*>(
                B + (size_t)(k0 + bK + p * 8) * N + ctaCol + bN);
        }
    };

    auto storeTile = [&](int buf) {
#pragma unroll
        for (int p = 0; p < 2; p++) {
            *reinterpret_cast<float4*>(&As[buf][aRow + p * 64][aCol]) = pa[p];
            *reinterpret_cast<float4*>(&Bs[buf][bK + p * 8][bN])      = pb[p];
        }
    };

    auto computeTile = [&](int buf) {
#pragma unroll
        for (int ks8 = 0; ks8 < 2; ks8++) {
            const int ks = ks8 * 8;
            uint32_t aHi[4][4], aLo[4][4];
#pragma unroll
            for (int t = 0; t < 4; t++) {
                int r = wRow + 16 * t + grp;
                float v0 = As[buf][r    ][ks + tig];
                float v1 = As[buf][r + 8][ks + tig];
                float v2 = As[buf][r    ][ks + tig + 4];
                float v3 = As[buf][r + 8][ks + tig + 4];
                split_tf32(v0, aHi[t][0], aLo[t][0]);
                split_tf32(v1, aHi[t][1], aLo[t][1]);
                split_tf32(v2, aHi[t][2], aLo[t][2]);
                split_tf32(v3, aHi[t][3], aLo[t][3]);
            }
            uint32_t bHi[4][2], bLo[4][2];
#pragma unroll
            for (int u = 0; u < 4; u++) {
                int c = wCol + 8 * u + grp;
                float w0 = Bs[buf][ks + tig    ][c];
                float w1 = Bs[buf][ks + tig + 4][c];
                split_tf32(w0, bHi[u][0], bLo[u][0]);
                split_tf32(w1, bHi[u][1], bLo[u][1]);
            }
#pragma unroll
            for (int t = 0; t < 4; t++)
#pragma unroll
                for (int u = 0; u < 4; u++) {
                    mma1688(acc[t][u], aLo[t], bHi[u]);
                    mma1688(acc[t][u], aHi[t], bLo[u]);
                    mma1688(acc[t][u], aHi[t], bHi[u]);
                }
        }
    };

    const int nT = K / GBK;
    loadTile(0);
    storeTile(0);
    __syncthreads();
    for (int it = 0; it < nT; it++) {
        if (it + 1 < nT) loadTile((it + 1) * GBK);
        computeTile(it & 1);
        if (it + 1 < nT) storeTile((it + 1) & 1);
        __syncthreads();
    }

#pragma unroll
    for (int t = 0; t < 4; t++) {
        int r0 = ctaRow + wRow + 16 * t + grp;
#pragma unroll
        for (int u = 0; u < 4; u++) {
            int c0 = ctaCol + wCol + 8 * u + tig * 2;
            if (r0 < M)
                *reinterpret_cast<float2*>(C + (size_t)r0 * N + c0) =
                    make_float2(acc[t][u][0], acc[t][u][1]);
            if (r0 + 8 < M)
                *reinterpret_cast<float2*>(C + (size_t)(r0 + 8) * N + c0) =
                    make_float2(acc[t][u][2], acc[t][u][3]);
        }
    }
}

// ---------------- CSR gather aggregation (F=256), fused bias + self term ----------------
// out[c] = bias + self[c]*h[c] + sum_{e in CSR[c]} cnorm[e] * h[crow[e]]
__global__ __launch_bounds__(256) void k_gather(
    const float* __restrict__ h,
    const int* __restrict__ rowptr,
    const int* __restrict__ crow,
    const float* __restrict__ cnorm,
    const float* __restrict__ bias,
    float* __restrict__ out, int n)
{
    int gw   = (blockIdx.x * blockDim.x + threadIdx.x) >> 5;
    int lane = threadIdx.x & 31;
    if (gw >= n) return;
    int beg = rowptr[gw], end = rowptr[gw + 1];

    const float4* hc = reinterpret_cast<const float4*>(h + (size_t)gw * HF);
    const float4* bb = reinterpret_cast<const float4*>(bias);
    float s = g_self[gw];
    float4 a0 = hc[lane], a1 = hc[lane + 32];
    float4 b0 = bb[lane], b1 = bb[lane + 32];
    float4 acc0 = make_float4(fmaf(s, a0.x, b0.x), fmaf(s, a0.y, b0.y),
                              fmaf(s, a0.z, b0.z), fmaf(s, a0.w, b0.w));
    float4 acc1 = make_float4(fmaf(s, a1.x, b1.x), fmaf(s, a1.y, b1.y),
                              fmaf(s, a1.z, b1.z), fmaf(s, a1.w, b1.w));

    int p = beg;
    // unrolled by 2 for MLP
    for (; p + 1 < end; p += 2) {
        int   r0i = crow[p],     r1i = crow[p + 1];
        float n0  = cnorm[p],    n1  = cnorm[p + 1];
        const float4* h0 = reinterpret_cast<const float4*>(h + (size_t)r0i * HF);
        const float4* h1 = reinterpret_cast<const float4*>(h + (size_t)r1i * HF);
        float4 v00 = h0[lane], v01 = h0[lane + 32];
        float4 v10 = h1[lane], v11 = h1[lane + 32];
        acc0.x = fmaf(n0, v00.x, acc0.x); acc0.y = fmaf(n0, v00.y, acc0.y);
        acc0.z = fmaf(n0, v00.z, acc0.z); acc0.w = fmaf(n0, v00.w, acc0.w);
        acc1.x = fmaf(n0, v01.x, acc1.x); acc1.y = fmaf(n0, v01.y, acc1.y);
        acc1.z = fmaf(n0, v01.z, acc1.z); acc1.w = fmaf(n0, v01.w, acc1.w);
        acc0.x = fmaf(n1, v10.x, acc0.x); acc0.y = fmaf(n1, v10.y, acc0.y);
        acc0.z = fmaf(n1, v10.z, acc0.z); acc0.w = fmaf(n1, v10.w, acc0.w);
        acc1.x = fmaf(n1, v11.x, acc1.x); acc1.y = fmaf(n1, v11.y, acc1.y);
        acc1.z = fmaf(n1, v11.z, acc1.z); acc1.w = fmaf(n1, v11.w, acc1.w);
    }
    if (p < end) {
        int   r = crow[p];
        float nm = cnorm[p];
        const float4* hr = reinterpret_cast<const float4*>(h + (size_t)r * HF);
        float4 v0 = hr[lane], v1 = hr[lane + 32];
        acc0.x = fmaf(nm, v0.x, acc0.x); acc0.y = fmaf(nm, v0.y, acc0.y);
        acc0.z = fmaf(nm, v0.z, acc0.z); acc0.w = fmaf(nm, v0.w, acc0.w);
        acc1.x = fmaf(nm, v1.x, acc1.x); acc1.y = fmaf(nm, v1.y, acc1.y);
        acc1.z = fmaf(nm, v1.z, acc1.z); acc1.w = fmaf(nm, v1.w, acc1.w);
    }

    float4* op = reinterpret_cast<float4*>(out + (size_t)gw * HF);
    op[lane]      = acc0;
    op[lane + 32] = acc1;
}

// ---------------- layer 3: skinny GEMM (256 -> 2) with fused BN2+ReLU ----------------
__global__ void k_gemm3(const float* __restrict__ A, const float* __restrict__ W3,
                        float* __restrict__ h3, int M)
{
    __shared__ float w0[HF], w1[HF];
    for (int i = threadIdx.x; i < HF; i += blockDim.x) {
        w0[i] = W3[i * 2 + 0];
        w1[i] = W3[i * 2 + 1];
    }
    __syncthreads();
    int gw   = (blockIdx.x * blockDim.x + threadIdx.x) >> 5;
    int lane = threadIdx.x & 31;
    if (gw >= M) return;
    const float* a = A + (size_t)gw * HF;
    float acc0 = 0.f, acc1 = 0.f;
#pragma unroll
    for (int j = 0; j < HF / 32; j++) {
        int k = j * 32 + lane;
        float av = fmaxf(fmaf(a[k], g_scale2[k], g_shift2[k]), 0.f);
        acc0 = fmaf(av, w0[k], acc0);
        acc1 = fmaf(av, w1[k], acc1);
    }
#pragma unroll
    for (int off = 16; off; off >>= 1) {
        acc0 += __shfl_xor_sync(0xffffffffu, acc0, off);
        acc1 += __shfl_xor_sync(0xffffffffu, acc1, off);
    }
    if (lane == 0) {
        h3[gw * 2 + 0] = acc0;
        h3[gw * 2 + 1] = acc1;
    }
}

// final gather (OUT=2): thread per node
__global__ void k_gather3(const float* __restrict__ h3,
                          const int* __restrict__ rowptr,
                          const int* __restrict__ crow,
                          const float* __restrict__ cnorm,
                          const float* __restrict__ b3,
                          float* __restrict__ out, int n)
{
    int c = blockIdx.x * blockDim.x + threadIdx.x;
    if (c >= n) return;
    float s = g_self[c];
    float acc0 = fmaf(s, h3[c * 2 + 0], b3[0]);
    float acc1 = fmaf(s, h3[c * 2 + 1], b3[1]);
    int beg = rowptr[c], end = rowptr[c + 1];
    for (int p = beg; p < end; p++) {
        int r = crow[p];
        float nm = cnorm[p];
        acc0 = fmaf(nm, h3[r * 2 + 0], acc0);
        acc1 = fmaf(nm, h3[r * 2 + 1], acc1);
    }
    out[c * 2 + 0] = acc0;
    out[c * 2 + 1] = acc1;
}

// ---------------- driver ----------------
extern "C" void kernel_launch(void* const* d_in, const int* in_sizes, int n_in,
                              void* d_out, int out_size)
{
    const float* x   = (const float*)d_in[0];
    const int*   ei  = (const int*)d_in[1];     // int32 (JAX x64 disabled)
    const float* ew  = (const float*)d_in[2];
    const float* W1  = (const float*)d_in[3];
    const float* b1  = (const float*)d_in[4];
    const float* g1  = (const float*)d_in[5];
    const float* be1 = (const float*)d_in[6];
    const float* m1  = (const float*)d_in[7];
    const float* v1  = (const float*)d_in[8];
    const float* W2  = (const float*)d_in[9];
    const float* b2  = (const float*)d_in[10];
    const float* g2  = (const float*)d_in[11];
    const float* be2 = (const float*)d_in[12];
    const float* m2  = (const float*)d_in[13];
    const float* v2  = (const float*)d_in[14];
    const float* W3  = (const float*)d_in[15];
    const float* b3  = (const float*)d_in[16];
    float* out = (float*)d_out;

    const int n = in_sizes[0] / F_IN;
    const int e = in_sizes[2];

    float *bufA, *bufB, *dinv, *selfn, *h3, *sc1, *sh1, *sc2, *sh2, *cnorm;
    int *degi, *rowptr, *cursor, *crow;
    cudaGetSymbolAddress((void**)&bufA,   g_bufA);
    cudaGetSymbolAddress((void**)&bufB,   g_bufB);
    cudaGetSymbolAddress((void**)&dinv,   g_dinv);
    cudaGetSymbolAddress((void**)&selfn,  g_self);
    cudaGetSymbolAddress((void**)&h3,     g_h3);
    cudaGetSymbolAddress((void**)&sc1,    g_scale1);
    cudaGetSymbolAddress((void**)&sh1,    g_shift1);
    cudaGetSymbolAddress((void**)&sc2,    g_scale2);
    cudaGetSymbolAddress((void**)&sh2,    g_shift2);
    cudaGetSymbolAddress((void**)&degi,   g_degi);
    cudaGetSymbolAddress((void**)&rowptr, g_rowptr);
    cudaGetSymbolAddress((void**)&cursor, g_cursor);
    cudaGetSymbolAddress((void**)&crow,   g_crow);
    cudaGetSymbolAddress((void**)&cnorm,  g_cnorm);

    const int* row = ei;
    const int* col = ei + e;

    const int T = 256;
    dim3 gemmGrid(HF / GBN, (n + GBM - 1) / GBM);

    // 1-3: degree prep
    k_init        <<<(n + T - 1) / T, T>>>(dinv, degi, cursor, n);
    k_count       <<<(e + T - 1) / T, T>>>(col, ew, dinv, degi, e);
    k_finalize_deg<<<(n + T - 1) / T, T>>>(dinv, selfn, n);
    // 4: GEMM1 (independent of graph prep) — positioned 4th for ncu capture
    tf32_gemm<<<gemmGrid, 256>>>(n, F_IN, HF, x, W1, bufA, nullptr, nullptr);
    // 5-6: CSR build
    k_scan   <<<1, 1024>>>(degi, rowptr, n);
    k_permute<<<(e + T - 1) / T, T>>>(row, col, ew, dinv, rowptr, cursor, crow, cnorm, e);
    // 7-8: BN folds
    k_bn_prep<<<1, HF>>>(g1, be1, m1, v1, sc1, sh1);
    k_bn_prep<<<1, HF>>>(g2, be2, m2, v2, sc2, sh2);

    // layer 1 aggregation
    k_gather<<<((size_t)n * 32 + T - 1) / T, T>>>(bufA, rowptr, crow, cnorm, b1, bufB, n);
    // layer 2
    tf32_gemm<<<gemmGrid, 256>>>(n, HF, HF, bufB, W2, bufA, sc1, sh1);
    k_gather<<<((size_t)n * 32 + T - 1) / T, T>>>(bufA, rowptr, crow, cnorm, b2, bufB, n);
    // layer 3
    k_gemm3  <<<((size_t)n * 32 + T - 1) / T, T>>>(bufB, W3, h3, n);
    k_gather3<<<(n + T - 1) / T, T>>>(h3, rowptr, crow, cnorm, b3, out, n);
}